// round 13
// baseline (speedup 1.0000x reference)
#include <cuda_runtime.h>

#define B_ROWS   16384
#define NFEAT    1024
#define FACTORS  64
#define TOTAL    524288
#define NBLOCKS  (TOTAL / 256)   // 2048

// Per-block partial sums (device global scratch; overwritten every replay)
__device__ float g_partials[NBLOCKS];

// G table (256 KB) is reused ~512x -> pin in L1. H streams -> evict_first.
__device__ __forceinline__ float2 ldg_el2(const void* p) {
    float2 v;
    asm("ld.global.nc.L1::evict_last.v2.f32 {%0,%1}, [%2];"
        : "=f"(v.x), "=f"(v.y) : "l"(p));
    return v;
}
__device__ __forceinline__ float2 ldg_ef2(const void* p) {
    float2 v;
    asm("ld.global.nc.L1::evict_first.v2.f32 {%0,%1}, [%2];"
        : "=f"(v.x), "=f"(v.y) : "l"(p));
    return v;
}

// ---------------------------------------------------------------------------
// 1) flat compute, depth-2 item pipeline, per-block partial output
// ---------------------------------------------------------------------------
__global__ __launch_bounds__(256, 6) void kgflex_flat2_kernel(
    const int*   __restrict__ user,
    const int*   __restrict__ sample_idx,
    const int*   __restrict__ feat_idx,
    const float* __restrict__ H,
    const float* __restrict__ G,
    const float* __restrict__ K)
{
    const int lane = threadIdx.x & 31;
    const int wid  = threadIdx.x >> 5;
    const int t    = blockIdx.x * 256 + threadIdx.x;   // exact cover

    // --- per-lane preload of this warp's 32 items
    const int b  = __ldg(sample_idx + t);
    const int n  = __ldg(feat_idx + t);
    const int u  = __ldg(user + b);
    const float kv = __ldg(K + (u << 10) + n);

    // --- stage precomputed BYTE offsets + kv: inner loop does zero shifts
    __shared__ int4 stage[8][32];
    stage[wid][lane] = make_int4(u << 8, n << 8, __float_as_int(kv), 0);
    __syncwarp();

    const char* Hb = (const char*)(H + 2 * lane);   // lane covers factors 2l,2l+1
    const char* Gb = (const char*)(G + 2 * lane);

    float acc = 0.0f;

    // --- depth-2 rotating-register pipeline
    float2 hbuf[2], gbuf[2];
    float  kbuf[2];
    {
        const int4 p0 = stage[wid][0];
        hbuf[0] = ldg_ef2(Hb + p0.x);
        gbuf[0] = ldg_el2(Gb + p0.y);
        kbuf[0] = __int_as_float(p0.z);
        const int4 p1 = stage[wid][1];
        hbuf[1] = ldg_ef2(Hb + p1.x);
        gbuf[1] = ldg_el2(Gb + p1.y);
        kbuf[1] = __int_as_float(p1.z);
    }

    #pragma unroll
    for (int j = 0; j < 32; ++j) {
        const int s = j & 1;
        const float2 h  = hbuf[s];
        const float2 g  = gbuf[s];
        const float  kc = kbuf[s];

        if (j + 2 < 32) {                     // prefetch item j+2 into slot s
            const int4 pn = stage[wid][j + 2];
            hbuf[s] = ldg_ef2(Hb + pn.x);
            gbuf[s] = ldg_el2(Gb + pn.y);
            kbuf[s] = __int_as_float(pn.z);
        }

        float d = h.x * g.x;
        d = fmaf(h.y, g.y, d);
        acc = fmaf(kc, d, acc);
    }

    // --- block reduction -> per-block partial (no atomics, no init needed)
    #pragma unroll
    for (int off = 16; off > 0; off >>= 1)
        acc += __shfl_xor_sync(0xFFFFFFFFu, acc, off);

    __shared__ float warp_sums[8];
    if (lane == 0) warp_sums[wid] = acc;
    __syncthreads();
    if (wid == 0) {
        float v = (lane < 8) ? warp_sums[lane] : 0.0f;
        #pragma unroll
        for (int off = 4; off > 0; off >>= 1)
            v += __shfl_xor_sync(0xFFFFFFFFu, v, off);
        if (lane == 0) g_partials[blockIdx.x] = v;
    }
}

// ---------------------------------------------------------------------------
// 2) final reduce: 2048 partials -> out[0]  (single block)
// ---------------------------------------------------------------------------
__global__ __launch_bounds__(1024) void reduce_kernel(float* __restrict__ out)
{
    const int tid = threadIdx.x;
    float v = g_partials[tid] + g_partials[tid + 1024];

    #pragma unroll
    for (int off = 16; off > 0; off >>= 1)
        v += __shfl_xor_sync(0xFFFFFFFFu, v, off);

    __shared__ float ws[32];
    if ((tid & 31) == 0) ws[tid >> 5] = v;
    __syncthreads();
    if (tid < 32) {
        float s = ws[tid];
        #pragma unroll
        for (int off = 16; off > 0; off >>= 1)
            s += __shfl_xor_sync(0xFFFFFFFFu, s, off);
        if (tid == 0) out[0] = s;
    }
}

// ---------------------------------------------------------------------------
extern "C" void kernel_launch(void* const* d_in, const int* in_sizes, int n_in,
                              void* d_out, int out_size)
{
    const int*   user       = (const int*)  d_in[0];
    const int*   sample_idx = (const int*)  d_in[1];
    const int*   feat_idx   = (const int*)  d_in[2];
    const float* H          = (const float*)d_in[3];
    const float* G          = (const float*)d_in[4];
    const float* K          = (const float*)d_in[5];
    float*       out        = (float*)d_out;

    (void)in_sizes; (void)n_in; (void)out_size;

    kgflex_flat2_kernel<<<NBLOCKS, 256>>>(user, sample_idx, feat_idx, H, G, K);
    reduce_kernel<<<1, 1024>>>(out);
}